// round 9
// baseline (speedup 1.0000x reference)
#include <cuda_runtime.h>
#include <cooperative_groups.h>
#include <cstdint>

namespace cg = cooperative_groups;

#define IMGS 8
#define HH 1024
#define WPX 1024
#define WW 32            // 32-bit words per row
#define WP 33            // padded row stride (bank-conflict-free)
#define MAXIT 64
#define NWORDS (IMGS * HH * WW)   // 262144

// Static global scratch (no allocations allowed)
__device__ uint32_t g_cbits[IMGS][HH][WW];    // endpoint bits (1 MB)
__device__ int      g_flag[IMGS * MAXIT];     // per-image per-iteration changed flags
__device__ double   g_pb[1024];               // BCE block partial sums
__device__ double   g_pc[1024];               // correction block partial sums
__device__ int      g_count;                  // finished-block counter for k_corr

// ---------------------------------------------------------------------------
// helpers
// ---------------------------------------------------------------------------
__device__ __forceinline__ uint32_t shW(uint32_t l, uint32_t m) {
    return __funnelshift_l(l, m, 1);     // west neighbor mask
}
__device__ __forceinline__ uint32_t shE(uint32_t m, uint32_t r) {
    return __funnelshift_r(m, r, 1);     // east neighbor mask
}

struct Bn4 { uint32_t n0, n1, n2, n3; };

__device__ __forceinline__ Bn4 bn8(uint32_t P2, uint32_t P3, uint32_t P4, uint32_t P5,
                                   uint32_t P6, uint32_t P7, uint32_t P8, uint32_t P9) {
    uint32_t s1 = P2 ^ P3 ^ P4, k1 = (P2 & P3) | (P4 & (P2 | P3));
    uint32_t s2 = P5 ^ P6 ^ P7, k2 = (P5 & P6) | (P7 & (P5 | P6));
    uint32_t s3 = s1 ^ s2 ^ P8, k3 = (s1 & s2) | (P8 & (s1 | s2));
    uint32_t n0 = s3 ^ P9,      k4 = s3 & P9;
    uint32_t s4 = k1 ^ k2 ^ k3, k5 = (k1 & k2) | (k3 & (k1 | k2));
    uint32_t n1 = s4 ^ k4,      k6 = s4 & k4;
    Bn4 r; r.n0 = n0; r.n1 = n1; r.n2 = k5 ^ k6; r.n3 = k5 & k6; return r;
}

template <int SUB>
__device__ __forceinline__ uint32_t thin_rows(const uint32_t* __restrict__ rowA,
                                              const uint32_t* __restrict__ rowC,
                                              const uint32_t* __restrict__ rowB,
                                              uint32_t* __restrict__ dst, int w0) {
    uint32_t a[10], c[10], b[10];
    #pragma unroll
    for (int i = 0; i < 10; ++i) {
        int w = w0 - 1 + i;
        bool ok = (w >= 0) && (w < WW);
        a[i] = ok ? rowA[w] : 0u;
        c[i] = ok ? rowC[w] : 0u;
        b[i] = ok ? rowB[w] : 0u;
    }
    uint32_t ch = 0;
    #pragma unroll
    for (int i = 0; i < 8; ++i) {
        uint32_t aL = a[i], aM = a[i + 1], aR = a[i + 2];
        uint32_t cL = c[i], cM = c[i + 1], cR = c[i + 2];
        uint32_t bL = b[i], bM = b[i + 1], bR = b[i + 2];
        uint32_t P2 = aM, P6 = bM;
        uint32_t P3 = shE(aM, aR), P4 = shE(cM, cR), P5 = shE(bM, bR);
        uint32_t P7 = shW(bL, bM), P8 = shW(cL, cM), P9 = shW(aL, aM);
        Bn4 n = bn8(P2, P3, P4, P5, P6, P7, P8, P9);
        uint32_t ge2 = n.n1 | n.n2 | n.n3;
        uint32_t ge7 = n.n3 | (n.n0 & n.n1 & n.n2);
        uint32_t condB = ge2 & ~ge7;
        uint32_t t, acc, multi;
        acc = ~P2 & P3; multi = 0u;
        t = ~P3 & P4; multi |= acc & t; acc |= t;
        t = ~P4 & P5; multi |= acc & t; acc |= t;
        t = ~P5 & P6; multi |= acc & t; acc |= t;
        t = ~P6 & P7; multi |= acc & t; acc |= t;
        t = ~P7 & P8; multi |= acc & t; acc |= t;
        t = ~P8 & P9; multi |= acc & t; acc |= t;
        t = ~P9 & P2; multi |= acc & t; acc |= t;
        uint32_t A1 = acc & ~multi;
        uint32_t e1, e2;
        if (SUB == 0) { e1 = ~(P2 & P4 & P6); e2 = ~(P4 & P6 & P8); }
        else          { e1 = ~(P2 & P4 & P8); e2 = ~(P2 & P6 & P8); }
        uint32_t rem = cM & condB & A1 & e1 & e2;
        dst[w0 + i] = cM ^ rem;
        ch |= rem;
    }
    return ch;
}

__device__ __forceinline__ void endpoint_rows(const uint32_t* __restrict__ rowA,
                                              const uint32_t* __restrict__ rowC,
                                              const uint32_t* __restrict__ rowB,
                                              int img, int gy, int w0) {
    uint32_t a[10], c[10], b[10];
    #pragma unroll
    for (int i = 0; i < 10; ++i) {
        int w = w0 - 1 + i;
        bool ok = (w >= 0) && (w < WW);
        a[i] = ok ? rowA[w] : 0u;
        c[i] = ok ? rowC[w] : 0u;
        b[i] = ok ? rowB[w] : 0u;
    }
    #pragma unroll
    for (int i = 0; i < 8; ++i) {
        uint32_t aL = a[i], aM = a[i + 1], aR = a[i + 2];
        uint32_t cL = c[i], cM = c[i + 1], cR = c[i + 2];
        uint32_t bL = b[i], bM = b[i + 1], bR = b[i + 2];
        uint32_t P2 = aM, P6 = bM;
        uint32_t P3 = shE(aM, aR), P4 = shE(cM, cR), P5 = shE(bM, bR);
        uint32_t P7 = shW(bL, bM), P8 = shW(cL, cM), P9 = shW(aL, aM);
        Bn4 n = bn8(P2, P3, P4, P5, P6, P7, P8, P9);
        g_cbits[img][gy][w0 + i] = cM & n.n0 & ~(n.n1 | n.n2 | n.n3);
    }
}

// ---------------------------------------------------------------------------
// SMEM-resident cluster thinning (proven round-5 code, unchanged)
// ---------------------------------------------------------------------------
template <int ROWS>
struct ThinSmem {
    uint32_t img[2][ROWS][WP];   // ping-pong tiles, padded stride
    uint32_t zero[WP];
    uint8_t  rowch[3][ROWS];     // rolling per-row change flags
    int      sflag;
};

template <int NC, int ROWS, int NTHR, typename SM>
__device__ void thin_main(SM* sm, const float* __restrict__ pred) {
    cg::cluster_group cluster = cg::this_cluster();
    const int tid  = threadIdx.x;
    const int lane = tid & 31;
    const int warp = tid >> 5;
    const int rank = (int)cluster.block_rank();
    const int img  = blockIdx.x / NC;
    int* flag = &g_flag[img * MAXIT];

    // ---- pack phase: threshold pred into sm->img[0] (float4 + shfl-OR) ----
    constexpr int NWARP = NTHR / 32;
    for (int r = warp; r < ROWS; r += NWARP) {
        const float4* row = (const float4*)(pred + ((size_t)img * HH + (size_t)rank * ROWS + r) * WPX);
        #pragma unroll
        for (int step = 0; step < 8; ++step) {
            float4 v = row[step * 32 + lane];
            uint32_t nib = (v.x >= 0.5f ? 1u : 0u) | (v.y >= 0.5f ? 2u : 0u)
                         | (v.z >= 0.5f ? 4u : 0u) | (v.w >= 0.5f ? 8u : 0u);
            uint32_t x = nib << (4 * (lane & 7));
            x |= __shfl_xor_sync(0xffffffffu, x, 1);
            x |= __shfl_xor_sync(0xffffffffu, x, 2);
            x |= __shfl_xor_sync(0xffffffffu, x, 4);
            if ((lane & 7) == 0) sm->img[0][r][step * 4 + (lane >> 3)] = x;
        }
    }
    if (tid < WP) sm->zero[tid] = 0u;
    if (rank == 0) { for (int i = tid; i < MAXIT; i += NTHR) flag[i] = 0; }
    if (blockIdx.x == 0 && tid == 0) g_count = 0;
    __threadfence();
    cluster.sync();

    SM* pprev = (rank > 0)      ? (SM*)cluster.map_shared_rank(sm, rank - 1) : nullptr;
    SM* pnext = (rank < NC - 1) ? (SM*)cluster.map_shared_rank(sm, rank + 1) : nullptr;

    const int ly = tid >> 2;
    const int w0 = (tid & 3) * 8;

    int cur = 0;
    for (int iter = 0; iter < MAXIT; ++iter) {
        if (tid == 0) sm->sflag = 0;
        __syncthreads();

        // ---- substep 0: img[0] -> img[1] ----
        {
            bool recompute = true;
            if (iter > 0) {
                int p1 = (cur + 2) % 3, p2 = (cur + 1) % 3;
                unsigned d = (unsigned)sm->rowch[p1][ly] | (unsigned)sm->rowch[p2][ly];
                if (ly > 0)        d |= (unsigned)sm->rowch[p1][ly - 1] | (unsigned)sm->rowch[p2][ly - 1];
                else if (pprev)    d |= (unsigned)pprev->rowch[p1][ROWS - 1] | (unsigned)pprev->rowch[p2][ROWS - 1];
                if (ly < ROWS - 1) d |= (unsigned)sm->rowch[p1][ly + 1] | (unsigned)sm->rowch[p2][ly + 1];
                else if (pnext)    d |= (unsigned)pnext->rowch[p1][0] | (unsigned)pnext->rowch[p2][0];
                recompute = (d != 0u);
            }
            uint32_t ch = 0;
            if (recompute) {
                const uint32_t* rA = (ly > 0) ? sm->img[0][ly - 1]
                                  : (pprev ? pprev->img[0][ROWS - 1] : sm->zero);
                const uint32_t* rB = (ly < ROWS - 1) ? sm->img[0][ly + 1]
                                  : (pnext ? pnext->img[0][0] : sm->zero);
                ch = thin_rows<0>(rA, sm->img[0][ly], rB, sm->img[1][ly], w0);
            }
            unsigned bal = __ballot_sync(0xffffffffu, ch != 0u);
            if ((tid & 3) == 0)
                sm->rowch[cur][ly] = (uint8_t)(((bal >> (lane & 28)) & 0xFu) ? 1 : 0);
            if (bal && lane == 0) sm->sflag = 1;
        }
        cluster.sync();
        cur = (cur + 1) % 3;

        // ---- substep 1: img[1] -> img[0] ----
        {
            bool recompute = true;
            if (iter > 0) {
                int p1 = (cur + 2) % 3, p2 = (cur + 1) % 3;
                unsigned d = (unsigned)sm->rowch[p1][ly] | (unsigned)sm->rowch[p2][ly];
                if (ly > 0)        d |= (unsigned)sm->rowch[p1][ly - 1] | (unsigned)sm->rowch[p2][ly - 1];
                else if (pprev)    d |= (unsigned)pprev->rowch[p1][ROWS - 1] | (unsigned)pprev->rowch[p2][ROWS - 1];
                if (ly < ROWS - 1) d |= (unsigned)sm->rowch[p1][ly + 1] | (unsigned)sm->rowch[p2][ly + 1];
                else if (pnext)    d |= (unsigned)pnext->rowch[p1][0] | (unsigned)pnext->rowch[p2][0];
                recompute = (d != 0u);
            }
            uint32_t ch = 0;
            if (recompute) {
                const uint32_t* rA = (ly > 0) ? sm->img[1][ly - 1]
                                  : (pprev ? pprev->img[1][ROWS - 1] : sm->zero);
                const uint32_t* rB = (ly < ROWS - 1) ? sm->img[1][ly + 1]
                                  : (pnext ? pnext->img[1][0] : sm->zero);
                ch = thin_rows<1>(rA, sm->img[1][ly], rB, sm->img[0][ly], w0);
            }
            unsigned bal = __ballot_sync(0xffffffffu, ch != 0u);
            if ((tid & 3) == 0)
                sm->rowch[cur][ly] = (uint8_t)(((bal >> (lane & 28)) & 0xFu) ? 1 : 0);
            if (bal && lane == 0) sm->sflag = 1;
        }
        __syncthreads();
        if (tid == 0 && sm->sflag) { atomicOr(&flag[iter], 1); __threadfence(); }
        cluster.sync();
        cur = (cur + 1) % 3;
        if (__ldcg(&flag[iter]) == 0) break;
    }

    // ---- fused endpoint extraction from img[0] ----
    {
        const uint32_t* rA = (ly > 0) ? sm->img[0][ly - 1]
                          : (pprev ? pprev->img[0][ROWS - 1] : sm->zero);
        const uint32_t* rB = (ly < ROWS - 1) ? sm->img[0][ly + 1]
                          : (pnext ? pnext->img[0][0] : sm->zero);
        endpoint_rows(rA, sm->img[0][ly], rB, img, rank * ROWS + ly, w0);
    }
    cluster.sync();
}

__global__ void __cluster_dims__(16, 1, 1) __launch_bounds__(256, 1)
k_thin16(const float* __restrict__ pred) {
    __shared__ ThinSmem<64> sm;
    thin_main<16, 64, 256>(&sm, pred);
}

__global__ void __cluster_dims__(8, 1, 1) __launch_bounds__(512, 1)
k_thin8(const float* __restrict__ pred) {
    __shared__ ThinSmem<128> sm;
    thin_main<8, 128, 512>(&sm, pred);
}

// ---------------------------------------------------------------------------
// K2: plain streaming BCE sum (skeleton-independent term). 1 word/thread.
// ---------------------------------------------------------------------------
__global__ void __launch_bounds__(256)
k_bce(const float* __restrict__ pred, const float* __restrict__ targ) {
    int i = blockIdx.x * 256 + threadIdx.x;       // word index 0..NWORDS-1
    const float4* p4 = (const float4*)(pred + (size_t)i * 32);
    const float4* t4 = (const float4*)(targ + (size_t)i * 32);
    float fsum = 0.0f;
    #pragma unroll
    for (int q = 0; q < 8; ++q) {
        float4 pv = __ldcs(p4 + q), tv = __ldcs(t4 + q);
        fsum += -(tv.x * __logf(pv.x) + (1.0f - tv.x) * __logf(1.0f - pv.x));
        fsum += -(tv.y * __logf(pv.y) + (1.0f - tv.y) * __logf(1.0f - pv.y));
        fsum += -(tv.z * __logf(pv.z) + (1.0f - tv.z) * __logf(1.0f - pv.z));
        fsum += -(tv.w * __logf(pv.w) + (1.0f - tv.w) * __logf(1.0f - pv.w));
    }
    __shared__ double sd[256];
    sd[threadIdx.x] = (double)fsum;
    __syncthreads();
    #pragma unroll
    for (int s = 128; s > 0; s >>= 1) {
        if (threadIdx.x < s) sd[threadIdx.x] += sd[threadIdx.x + s];
        __syncthreads();
    }
    if (threadIdx.x == 0) g_pb[blockIdx.x] = sd[0];
}

// ---------------------------------------------------------------------------
// K3: correction  sum (60N-1)*L over pixels with N>0 only.
// cbits staged in smem; uncovered words never touch pred/targ.
// Last block folds in g_pb for the deterministic final reduction.
// ---------------------------------------------------------------------------
#define FA3(a, b, c, s, cy) { uint32_t _x = (a) ^ (b); (s) = _x ^ (c); (cy) = ((a) & (b)) | ((c) & _x); }

__global__ void __launch_bounds__(256) k_corr(const float* __restrict__ pred,
                                              const float* __restrict__ targ,
                                              float* __restrict__ out) {
    const int img = blockIdx.x >> 7;
    const int y0  = (blockIdx.x & 127) * 8;      // block covers rows y0..y0+7
    const uint32_t* C = &g_cbits[img][0][0];
    const int tid = threadIdx.x;

    __shared__ uint32_t tile[16][WW + 1];        // rows y0-4 .. y0+11
    #pragma unroll
    for (int k = 0; k < 2; ++k) {
        int idx = tid + k * 256;
        int sr = idx >> 5, sw = idx & 31;
        int gy = y0 - 4 + sr;
        tile[sr][sw] = (gy >= 0 && gy < HH) ? C[gy * WW + sw] : 0u;
    }
    __syncthreads();

    const int w = tid & 31, lr = tid >> 5;       // word, local row
    const int y = y0 + lr;

    uint32_t rlo[9], rhi[9], orAll = 0;
    #pragma unroll
    for (int d = 0; d < 9; ++d) {
        uint32_t M = tile[lr + d][w];
        uint32_t L = (w > 0)  ? tile[lr + d][w - 1] : 0u;
        uint32_t R = (w < 31) ? tile[lr + d][w + 1] : 0u;
        rlo[d] = (L >> 28) | (M << 4);
        rhi[d] = (M >> 28) | ((R & 0xFu) << 4);
        orAll |= rlo[d] | rhi[d];
    }

    float fsum = 0.0f;
    if (orAll) {
        uint32_t S0l, S1l, S2l, S3l, S0h, S1h, S2h, S3h;
        {
            uint32_t s1, c1, s2, c2, s3, c3, c4, s5, c5, c6;
            FA3(rlo[0], rlo[1], rlo[2], s1, c1);
            FA3(rlo[3], rlo[4], rlo[5], s2, c2);
            FA3(rlo[6], rlo[7], rlo[8], s3, c3);
            FA3(s1, s2, s3, S0l, c4);
            FA3(c1, c2, c3, s5, c5);
            S1l = s5 ^ c4; c6 = s5 & c4;
            S2l = c5 ^ c6; S3l = c5 & c6;
            FA3(rhi[0], rhi[1], rhi[2], s1, c1);
            FA3(rhi[3], rhi[4], rhi[5], s2, c2);
            FA3(rhi[6], rhi[7], rhi[8], s3, c3);
            FA3(s1, s2, s3, S0h, c4);
            FA3(c1, c2, c3, s5, c5);
            S1h = s5 ^ c4; c6 = s5 & c4;
            S2h = c5 ^ c6; S3h = c5 & c6;
        }

        size_t poff = ((size_t)img * HH + y) * WPX + (size_t)w * 32;
        const float4* p4 = (const float4*)(pred + poff);
        const float4* t4 = (const float4*)(targ + poff);
        #pragma unroll
        for (int q = 0; q < 8; ++q) {
            float4 pv = p4[q], tv = t4[q];
            float pa[4] = {pv.x, pv.y, pv.z, pv.w};
            float ta[4] = {tv.x, tv.y, tv.z, tv.w};
            #pragma unroll
            for (int j = 0; j < 4; ++j) {
                int k = q * 4 + j;
                int nsum = __popc(__funnelshift_r(S0l, S0h, k) & 0x1FFu)
                         + (__popc(__funnelshift_r(S1l, S1h, k) & 0x1FFu) << 1)
                         + (__popc(__funnelshift_r(S2l, S2h, k) & 0x1FFu) << 2)
                         + (__popc(__funnelshift_r(S3l, S3h, k) & 0x1FFu) << 3);
                if (nsum) {
                    float p = pa[j], t = ta[j];
                    float Lb = -(t * __logf(p) + (1.0f - t) * __logf(1.0f - p));
                    fsum += (60.0f * (float)nsum - 1.0f) * Lb;
                }
            }
        }
    }

    __shared__ double sd[256];
    sd[tid] = (double)fsum;
    __syncthreads();
    #pragma unroll
    for (int s = 128; s > 0; s >>= 1) {
        if (tid < s) sd[tid] += sd[tid + s];
        __syncthreads();
    }
    __shared__ int slast;
    if (tid == 0) {
        g_pc[blockIdx.x] = sd[0];
        __threadfence();
        slast = (atomicAdd(&g_count, 1) == (int)gridDim.x - 1);
    }
    __syncthreads();
    if (!slast) return;

    // deterministic fixed-order final reduction: 1024 corr + 1024 bce partials
    double v = __ldcg(&g_pc[tid]) + __ldcg(&g_pc[tid + 256])
             + __ldcg(&g_pc[tid + 512]) + __ldcg(&g_pc[tid + 768])
             + __ldcg(&g_pb[tid]) + __ldcg(&g_pb[tid + 256])
             + __ldcg(&g_pb[tid + 512]) + __ldcg(&g_pb[tid + 768]);
    sd[tid] = v;
    __syncthreads();
    #pragma unroll
    for (int s = 128; s > 0; s >>= 1) {
        if (tid < s) sd[tid] += sd[tid + s];
        __syncthreads();
    }
    if (tid == 0) out[0] = (float)(sd[0] * (1.0 / ((double)IMGS * HH * WPX)));
}

// ---------------------------------------------------------------------------
extern "C" void kernel_launch(void* const* d_in, const int* in_sizes, int n_in,
                              void* d_out, int out_size) {
    (void)in_sizes; (void)n_in; (void)out_size;
    const float* pred = (const float*)d_in[0];
    const float* targ = (const float*)d_in[1];
    float* out = (float*)d_out;

    cudaError_t e = cudaFuncSetAttribute(
        (const void*)k_thin16, cudaFuncAttributeNonPortableClusterSizeAllowed, 1);
    if (e == cudaSuccess) {
        k_thin16<<<128, 256>>>(pred);
    } else {
        (void)cudaGetLastError();   // clear sticky error before capture continues
        k_thin8<<<64, 512>>>(pred);
    }

    k_bce<<<1024, 256>>>(pred, targ);
    k_corr<<<1024, 256>>>(pred, targ, out);
}

// round 10
// speedup vs baseline: 1.0407x; 1.0407x over previous
#include <cuda_runtime.h>
#include <cooperative_groups.h>
#include <cstdint>

namespace cg = cooperative_groups;

#define IMGS 8
#define HH 1024
#define WPX 1024
#define WW 32            // 32-bit words per row
#define WP 33            // padded row stride (bank-conflict-free)
#define MAXIT 64
#define NWORDS (IMGS * HH * WW)   // 262144

// Static global scratch (no allocations allowed)
__device__ uint32_t g_cbits[IMGS][HH][WW];    // endpoint bits (1 MB)
__device__ int      g_flag[IMGS * MAXIT];     // per-image per-iteration changed flags
__device__ float    g_lb[IMGS * HH * WPX];    // per-pixel BCE values (32 MB)
__device__ double   g_pb[1024];               // BCE block partial sums
__device__ double   g_pc[1024];               // correction block partial sums
__device__ int      g_count;                  // finished-block counter for k_corr

// ---------------------------------------------------------------------------
// helpers
// ---------------------------------------------------------------------------
__device__ __forceinline__ uint32_t shW(uint32_t l, uint32_t m) {
    return __funnelshift_l(l, m, 1);     // west neighbor mask
}
__device__ __forceinline__ uint32_t shE(uint32_t m, uint32_t r) {
    return __funnelshift_r(m, r, 1);     // east neighbor mask
}

struct Bn4 { uint32_t n0, n1, n2, n3; };

__device__ __forceinline__ Bn4 bn8(uint32_t P2, uint32_t P3, uint32_t P4, uint32_t P5,
                                   uint32_t P6, uint32_t P7, uint32_t P8, uint32_t P9) {
    uint32_t s1 = P2 ^ P3 ^ P4, k1 = (P2 & P3) | (P4 & (P2 | P3));
    uint32_t s2 = P5 ^ P6 ^ P7, k2 = (P5 & P6) | (P7 & (P5 | P6));
    uint32_t s3 = s1 ^ s2 ^ P8, k3 = (s1 & s2) | (P8 & (s1 | s2));
    uint32_t n0 = s3 ^ P9,      k4 = s3 & P9;
    uint32_t s4 = k1 ^ k2 ^ k3, k5 = (k1 & k2) | (k3 & (k1 | k2));
    uint32_t n1 = s4 ^ k4,      k6 = s4 & k4;
    Bn4 r; r.n0 = n0; r.n1 = n1; r.n2 = k5 ^ k6; r.n3 = k5 & k6; return r;
}

template <int SUB>
__device__ __forceinline__ uint32_t thin_rows(const uint32_t* __restrict__ rowA,
                                              const uint32_t* __restrict__ rowC,
                                              const uint32_t* __restrict__ rowB,
                                              uint32_t* __restrict__ dst, int w0) {
    uint32_t a[10], c[10], b[10];
    #pragma unroll
    for (int i = 0; i < 10; ++i) {
        int w = w0 - 1 + i;
        bool ok = (w >= 0) && (w < WW);
        a[i] = ok ? rowA[w] : 0u;
        c[i] = ok ? rowC[w] : 0u;
        b[i] = ok ? rowB[w] : 0u;
    }
    uint32_t ch = 0;
    #pragma unroll
    for (int i = 0; i < 8; ++i) {
        uint32_t aL = a[i], aM = a[i + 1], aR = a[i + 2];
        uint32_t cL = c[i], cM = c[i + 1], cR = c[i + 2];
        uint32_t bL = b[i], bM = b[i + 1], bR = b[i + 2];
        uint32_t P2 = aM, P6 = bM;
        uint32_t P3 = shE(aM, aR), P4 = shE(cM, cR), P5 = shE(bM, bR);
        uint32_t P7 = shW(bL, bM), P8 = shW(cL, cM), P9 = shW(aL, aM);
        Bn4 n = bn8(P2, P3, P4, P5, P6, P7, P8, P9);
        uint32_t ge2 = n.n1 | n.n2 | n.n3;
        uint32_t ge7 = n.n3 | (n.n0 & n.n1 & n.n2);
        uint32_t condB = ge2 & ~ge7;
        uint32_t t, acc, multi;
        acc = ~P2 & P3; multi = 0u;
        t = ~P3 & P4; multi |= acc & t; acc |= t;
        t = ~P4 & P5; multi |= acc & t; acc |= t;
        t = ~P5 & P6; multi |= acc & t; acc |= t;
        t = ~P6 & P7; multi |= acc & t; acc |= t;
        t = ~P7 & P8; multi |= acc & t; acc |= t;
        t = ~P8 & P9; multi |= acc & t; acc |= t;
        t = ~P9 & P2; multi |= acc & t; acc |= t;
        uint32_t A1 = acc & ~multi;
        uint32_t e1, e2;
        if (SUB == 0) { e1 = ~(P2 & P4 & P6); e2 = ~(P4 & P6 & P8); }
        else          { e1 = ~(P2 & P4 & P8); e2 = ~(P2 & P6 & P8); }
        uint32_t rem = cM & condB & A1 & e1 & e2;
        dst[w0 + i] = cM ^ rem;
        ch |= rem;
    }
    return ch;
}

__device__ __forceinline__ void endpoint_rows(const uint32_t* __restrict__ rowA,
                                              const uint32_t* __restrict__ rowC,
                                              const uint32_t* __restrict__ rowB,
                                              int img, int gy, int w0) {
    uint32_t a[10], c[10], b[10];
    #pragma unroll
    for (int i = 0; i < 10; ++i) {
        int w = w0 - 1 + i;
        bool ok = (w >= 0) && (w < WW);
        a[i] = ok ? rowA[w] : 0u;
        c[i] = ok ? rowC[w] : 0u;
        b[i] = ok ? rowB[w] : 0u;
    }
    #pragma unroll
    for (int i = 0; i < 8; ++i) {
        uint32_t aL = a[i], aM = a[i + 1], aR = a[i + 2];
        uint32_t cL = c[i], cM = c[i + 1], cR = c[i + 2];
        uint32_t bL = b[i], bM = b[i + 1], bR = b[i + 2];
        uint32_t P2 = aM, P6 = bM;
        uint32_t P3 = shE(aM, aR), P4 = shE(cM, cR), P5 = shE(bM, bR);
        uint32_t P7 = shW(bL, bM), P8 = shW(cL, cM), P9 = shW(aL, aM);
        Bn4 n = bn8(P2, P3, P4, P5, P6, P7, P8, P9);
        g_cbits[img][gy][w0 + i] = cM & n.n0 & ~(n.n1 | n.n2 | n.n3);
    }
}

// ---------------------------------------------------------------------------
// SMEM-resident cluster thinning (proven round-5 code, unchanged)
// ---------------------------------------------------------------------------
template <int ROWS>
struct ThinSmem {
    uint32_t img[2][ROWS][WP];   // ping-pong tiles, padded stride
    uint32_t zero[WP];
    uint8_t  rowch[3][ROWS];     // rolling per-row change flags
    int      sflag;
};

template <int NC, int ROWS, int NTHR, typename SM>
__device__ void thin_main(SM* sm, const float* __restrict__ pred) {
    cg::cluster_group cluster = cg::this_cluster();
    const int tid  = threadIdx.x;
    const int lane = tid & 31;
    const int warp = tid >> 5;
    const int rank = (int)cluster.block_rank();
    const int img  = blockIdx.x / NC;
    int* flag = &g_flag[img * MAXIT];

    // ---- pack phase: threshold pred into sm->img[0] (float4 + shfl-OR) ----
    constexpr int NWARP = NTHR / 32;
    for (int r = warp; r < ROWS; r += NWARP) {
        const float4* row = (const float4*)(pred + ((size_t)img * HH + (size_t)rank * ROWS + r) * WPX);
        #pragma unroll
        for (int step = 0; step < 8; ++step) {
            float4 v = row[step * 32 + lane];
            uint32_t nib = (v.x >= 0.5f ? 1u : 0u) | (v.y >= 0.5f ? 2u : 0u)
                         | (v.z >= 0.5f ? 4u : 0u) | (v.w >= 0.5f ? 8u : 0u);
            uint32_t x = nib << (4 * (lane & 7));
            x |= __shfl_xor_sync(0xffffffffu, x, 1);
            x |= __shfl_xor_sync(0xffffffffu, x, 2);
            x |= __shfl_xor_sync(0xffffffffu, x, 4);
            if ((lane & 7) == 0) sm->img[0][r][step * 4 + (lane >> 3)] = x;
        }
    }
    if (tid < WP) sm->zero[tid] = 0u;
    if (rank == 0) { for (int i = tid; i < MAXIT; i += NTHR) flag[i] = 0; }
    if (blockIdx.x == 0 && tid == 0) g_count = 0;
    __threadfence();
    cluster.sync();

    SM* pprev = (rank > 0)      ? (SM*)cluster.map_shared_rank(sm, rank - 1) : nullptr;
    SM* pnext = (rank < NC - 1) ? (SM*)cluster.map_shared_rank(sm, rank + 1) : nullptr;

    const int ly = tid >> 2;
    const int w0 = (tid & 3) * 8;

    int cur = 0;
    for (int iter = 0; iter < MAXIT; ++iter) {
        if (tid == 0) sm->sflag = 0;
        __syncthreads();

        // ---- substep 0: img[0] -> img[1] ----
        {
            bool recompute = true;
            if (iter > 0) {
                int p1 = (cur + 2) % 3, p2 = (cur + 1) % 3;
                unsigned d = (unsigned)sm->rowch[p1][ly] | (unsigned)sm->rowch[p2][ly];
                if (ly > 0)        d |= (unsigned)sm->rowch[p1][ly - 1] | (unsigned)sm->rowch[p2][ly - 1];
                else if (pprev)    d |= (unsigned)pprev->rowch[p1][ROWS - 1] | (unsigned)pprev->rowch[p2][ROWS - 1];
                if (ly < ROWS - 1) d |= (unsigned)sm->rowch[p1][ly + 1] | (unsigned)sm->rowch[p2][ly + 1];
                else if (pnext)    d |= (unsigned)pnext->rowch[p1][0] | (unsigned)pnext->rowch[p2][0];
                recompute = (d != 0u);
            }
            uint32_t ch = 0;
            if (recompute) {
                const uint32_t* rA = (ly > 0) ? sm->img[0][ly - 1]
                                  : (pprev ? pprev->img[0][ROWS - 1] : sm->zero);
                const uint32_t* rB = (ly < ROWS - 1) ? sm->img[0][ly + 1]
                                  : (pnext ? pnext->img[0][0] : sm->zero);
                ch = thin_rows<0>(rA, sm->img[0][ly], rB, sm->img[1][ly], w0);
            }
            unsigned bal = __ballot_sync(0xffffffffu, ch != 0u);
            if ((tid & 3) == 0)
                sm->rowch[cur][ly] = (uint8_t)(((bal >> (lane & 28)) & 0xFu) ? 1 : 0);
            if (bal && lane == 0) sm->sflag = 1;
        }
        cluster.sync();
        cur = (cur + 1) % 3;

        // ---- substep 1: img[1] -> img[0] ----
        {
            bool recompute = true;
            if (iter > 0) {
                int p1 = (cur + 2) % 3, p2 = (cur + 1) % 3;
                unsigned d = (unsigned)sm->rowch[p1][ly] | (unsigned)sm->rowch[p2][ly];
                if (ly > 0)        d |= (unsigned)sm->rowch[p1][ly - 1] | (unsigned)sm->rowch[p2][ly - 1];
                else if (pprev)    d |= (unsigned)pprev->rowch[p1][ROWS - 1] | (unsigned)pprev->rowch[p2][ROWS - 1];
                if (ly < ROWS - 1) d |= (unsigned)sm->rowch[p1][ly + 1] | (unsigned)sm->rowch[p2][ly + 1];
                else if (pnext)    d |= (unsigned)pnext->rowch[p1][0] | (unsigned)pnext->rowch[p2][0];
                recompute = (d != 0u);
            }
            uint32_t ch = 0;
            if (recompute) {
                const uint32_t* rA = (ly > 0) ? sm->img[1][ly - 1]
                                  : (pprev ? pprev->img[1][ROWS - 1] : sm->zero);
                const uint32_t* rB = (ly < ROWS - 1) ? sm->img[1][ly + 1]
                                  : (pnext ? pnext->img[1][0] : sm->zero);
                ch = thin_rows<1>(rA, sm->img[1][ly], rB, sm->img[0][ly], w0);
            }
            unsigned bal = __ballot_sync(0xffffffffu, ch != 0u);
            if ((tid & 3) == 0)
                sm->rowch[cur][ly] = (uint8_t)(((bal >> (lane & 28)) & 0xFu) ? 1 : 0);
            if (bal && lane == 0) sm->sflag = 1;
        }
        __syncthreads();
        if (tid == 0 && sm->sflag) { atomicOr(&flag[iter], 1); __threadfence(); }
        cluster.sync();
        cur = (cur + 1) % 3;
        if (__ldcg(&flag[iter]) == 0) break;
    }

    // ---- fused endpoint extraction from img[0] ----
    {
        const uint32_t* rA = (ly > 0) ? sm->img[0][ly - 1]
                          : (pprev ? pprev->img[0][ROWS - 1] : sm->zero);
        const uint32_t* rB = (ly < ROWS - 1) ? sm->img[0][ly + 1]
                          : (pnext ? pnext->img[0][0] : sm->zero);
        endpoint_rows(rA, sm->img[0][ly], rB, img, rank * ROWS + ly, w0);
    }
    cluster.sync();
}

__global__ void __cluster_dims__(16, 1, 1) __launch_bounds__(256, 1)
k_thin16(const float* __restrict__ pred) {
    __shared__ ThinSmem<64> sm;
    thin_main<16, 64, 256>(&sm, pred);
}

__global__ void __cluster_dims__(8, 1, 1) __launch_bounds__(512, 1)
k_thin8(const float* __restrict__ pred) {
    __shared__ ThinSmem<128> sm;
    thin_main<8, 128, 512>(&sm, pred);
}

// ---------------------------------------------------------------------------
// K2: streaming BCE: per-pixel L stored to g_lb (L2-resident) + partial sums.
// Runs CONCURRENTLY with thinning (independent of the skeleton).
// ---------------------------------------------------------------------------
__global__ void __launch_bounds__(256)
k_bce(const float* __restrict__ pred, const float* __restrict__ targ) {
    int i = blockIdx.x * 256 + threadIdx.x;       // word index 0..NWORDS-1
    const float4* p4 = (const float4*)(pred + (size_t)i * 32);
    const float4* t4 = (const float4*)(targ + (size_t)i * 32);
    float4* l4 = (float4*)(g_lb + (size_t)i * 32);
    float fsum = 0.0f;
    #pragma unroll
    for (int q = 0; q < 8; ++q) {
        float4 pv = __ldcs(p4 + q), tv = __ldcs(t4 + q);
        float4 lv;
        lv.x = -(tv.x * __logf(pv.x) + (1.0f - tv.x) * __logf(1.0f - pv.x));
        lv.y = -(tv.y * __logf(pv.y) + (1.0f - tv.y) * __logf(1.0f - pv.y));
        lv.z = -(tv.z * __logf(pv.z) + (1.0f - tv.z) * __logf(1.0f - pv.z));
        lv.w = -(tv.w * __logf(pv.w) + (1.0f - tv.w) * __logf(1.0f - pv.w));
        l4[q] = lv;                                // default policy -> L2 resident
        fsum += lv.x + lv.y + lv.z + lv.w;
    }
    __shared__ double sd[256];
    sd[threadIdx.x] = (double)fsum;
    __syncthreads();
    #pragma unroll
    for (int s = 128; s > 0; s >>= 1) {
        if (threadIdx.x < s) sd[threadIdx.x] += sd[threadIdx.x + s];
        __syncthreads();
    }
    if (threadIdx.x == 0) g_pb[blockIdx.x] = sd[0];
}

// ---------------------------------------------------------------------------
// K3: correction  sum (60N-1)*L over pixels with N>0, reading cached L.
// Last block folds in g_pb for the deterministic final reduction.
// ---------------------------------------------------------------------------
#define FA3(a, b, c, s, cy) { uint32_t _x = (a) ^ (b); (s) = _x ^ (c); (cy) = ((a) & (b)) | ((c) & _x); }

__global__ void __launch_bounds__(256) k_corr(float* __restrict__ out) {
    const int img = blockIdx.x >> 7;
    const int y0  = (blockIdx.x & 127) * 8;      // block covers rows y0..y0+7
    const uint32_t* C = &g_cbits[img][0][0];
    const int tid = threadIdx.x;

    __shared__ uint32_t tile[16][WW + 1];        // rows y0-4 .. y0+11
    #pragma unroll
    for (int k = 0; k < 2; ++k) {
        int idx = tid + k * 256;
        int sr = idx >> 5, sw = idx & 31;
        int gy = y0 - 4 + sr;
        tile[sr][sw] = (gy >= 0 && gy < HH) ? C[gy * WW + sw] : 0u;
    }
    __syncthreads();

    const int w = tid & 31, lr = tid >> 5;       // word, local row
    const int y = y0 + lr;

    uint32_t rlo[9], rhi[9], orAll = 0;
    #pragma unroll
    for (int d = 0; d < 9; ++d) {
        uint32_t M = tile[lr + d][w];
        uint32_t L = (w > 0)  ? tile[lr + d][w - 1] : 0u;
        uint32_t R = (w < 31) ? tile[lr + d][w + 1] : 0u;
        rlo[d] = (L >> 28) | (M << 4);
        rhi[d] = (M >> 28) | ((R & 0xFu) << 4);
        orAll |= rlo[d] | rhi[d];
    }

    float fsum = 0.0f;
    if (orAll) {
        uint32_t S0l, S1l, S2l, S3l, S0h, S1h, S2h, S3h;
        {
            uint32_t s1, c1, s2, c2, s3, c3, c4, s5, c5, c6;
            FA3(rlo[0], rlo[1], rlo[2], s1, c1);
            FA3(rlo[3], rlo[4], rlo[5], s2, c2);
            FA3(rlo[6], rlo[7], rlo[8], s3, c3);
            FA3(s1, s2, s3, S0l, c4);
            FA3(c1, c2, c3, s5, c5);
            S1l = s5 ^ c4; c6 = s5 & c4;
            S2l = c5 ^ c6; S3l = c5 & c6;
            FA3(rhi[0], rhi[1], rhi[2], s1, c1);
            FA3(rhi[3], rhi[4], rhi[5], s2, c2);
            FA3(rhi[6], rhi[7], rhi[8], s3, c3);
            FA3(s1, s2, s3, S0h, c4);
            FA3(c1, c2, c3, s5, c5);
            S1h = s5 ^ c4; c6 = s5 & c4;
            S2h = c5 ^ c6; S3h = c5 & c6;
        }

        const float4* l4 = (const float4*)(g_lb + (((size_t)img * HH + y) * WPX + (size_t)w * 32));
        #pragma unroll
        for (int q = 0; q < 8; ++q) {
            float4 lv = l4[q];
            float la[4] = {lv.x, lv.y, lv.z, lv.w};
            #pragma unroll
            for (int j = 0; j < 4; ++j) {
                int k = q * 4 + j;
                int nsum = __popc(__funnelshift_r(S0l, S0h, k) & 0x1FFu)
                         + (__popc(__funnelshift_r(S1l, S1h, k) & 0x1FFu) << 1)
                         + (__popc(__funnelshift_r(S2l, S2h, k) & 0x1FFu) << 2)
                         + (__popc(__funnelshift_r(S3l, S3h, k) & 0x1FFu) << 3);
                if (nsum) fsum += (60.0f * (float)nsum - 1.0f) * la[j];
            }
        }
    }

    __shared__ double sd[256];
    sd[tid] = (double)fsum;
    __syncthreads();
    #pragma unroll
    for (int s = 128; s > 0; s >>= 1) {
        if (tid < s) sd[tid] += sd[tid + s];
        __syncthreads();
    }
    __shared__ int slast;
    if (tid == 0) {
        g_pc[blockIdx.x] = sd[0];
        __threadfence();
        slast = (atomicAdd(&g_count, 1) == (int)gridDim.x - 1);
    }
    __syncthreads();
    if (!slast) return;

    // deterministic fixed-order final reduction: 1024 corr + 1024 bce partials
    double v = __ldcg(&g_pc[tid]) + __ldcg(&g_pc[tid + 256])
             + __ldcg(&g_pc[tid + 512]) + __ldcg(&g_pc[tid + 768])
             + __ldcg(&g_pb[tid]) + __ldcg(&g_pb[tid + 256])
             + __ldcg(&g_pb[tid + 512]) + __ldcg(&g_pb[tid + 768]);
    sd[tid] = v;
    __syncthreads();
    #pragma unroll
    for (int s = 128; s > 0; s >>= 1) {
        if (tid < s) sd[tid] += sd[tid + s];
        __syncthreads();
    }
    if (tid == 0) out[0] = (float)(sd[0] * (1.0 / ((double)IMGS * HH * WPX)));
}

// ---------------------------------------------------------------------------
extern "C" void kernel_launch(void* const* d_in, const int* in_sizes, int n_in,
                              void* d_out, int out_size) {
    (void)in_sizes; (void)n_in; (void)out_size;
    const float* pred = (const float*)d_in[0];
    const float* targ = (const float*)d_in[1];
    float* out = (float*)d_out;

    // One-time resource setup (resource handles only; the launched WORK is
    // identical on every call). First call is the uncaptured correctness run.
    static cudaStream_t s2 = 0;
    static cudaEvent_t ev0 = 0, ev1 = 0;
    static int fork_ok = -1;
    if (fork_ok < 0) {
        fork_ok = (cudaStreamCreateWithFlags(&s2, cudaStreamNonBlocking) == cudaSuccess &&
                   cudaEventCreateWithFlags(&ev0, cudaEventDisableTiming) == cudaSuccess &&
                   cudaEventCreateWithFlags(&ev1, cudaEventDisableTiming) == cudaSuccess) ? 1 : 0;
        (void)cudaGetLastError();
    }

    cudaError_t e = cudaFuncSetAttribute(
        (const void*)k_thin16, cudaFuncAttributeNonPortableClusterSizeAllowed, 1);
    bool use16 = (e == cudaSuccess);
    if (!use16) (void)cudaGetLastError();

    if (fork_ok == 1) {
        // fork: thin on the main (capture) stream, BCE concurrently on s2
        cudaEventRecord(ev0, 0);
        cudaStreamWaitEvent(s2, ev0, 0);
        if (use16) k_thin16<<<128, 256>>>(pred);
        else       k_thin8<<<64, 512>>>(pred);
        k_bce<<<1024, 256, 0, s2>>>(pred, targ);
        cudaEventRecord(ev1, s2);
        cudaStreamWaitEvent(0, ev1, 0);          // join
    } else {
        if (use16) k_thin16<<<128, 256>>>(pred);
        else       k_thin8<<<64, 512>>>(pred);
        k_bce<<<1024, 256>>>(pred, targ);
    }

    k_corr<<<1024, 256>>>(out);
}

// round 11
// speedup vs baseline: 1.4696x; 1.4122x over previous
#include <cuda_runtime.h>
#include <cooperative_groups.h>
#include <cstdint>

namespace cg = cooperative_groups;

#define IMGS 8
#define HH 1024
#define WPX 1024
#define WW 32            // 32-bit words per row
#define WP 33            // padded row stride (bank-conflict-free)
#define MAXIT 64

// Static global scratch (no allocations allowed)
__device__ uint32_t g_cbits[IMGS][HH][WW];    // endpoint bits (1 MB)
__device__ int      g_flag[IMGS * MAXIT];     // per-image per-iteration changed flags
__device__ double   g_partial[1024];          // block partial sums
__device__ int      g_count;                  // finished-block counter for k_loss

// ---------------------------------------------------------------------------
// helpers
// ---------------------------------------------------------------------------
__device__ __forceinline__ uint32_t shW(uint32_t l, uint32_t m) {
    return __funnelshift_l(l, m, 1);     // west neighbor mask
}
__device__ __forceinline__ uint32_t shE(uint32_t m, uint32_t r) {
    return __funnelshift_r(m, r, 1);     // east neighbor mask
}

struct Bn4 { uint32_t n0, n1, n2, n3; };

__device__ __forceinline__ Bn4 bn8(uint32_t P2, uint32_t P3, uint32_t P4, uint32_t P5,
                                   uint32_t P6, uint32_t P7, uint32_t P8, uint32_t P9) {
    uint32_t s1 = P2 ^ P3 ^ P4, k1 = (P2 & P3) | (P4 & (P2 | P3));
    uint32_t s2 = P5 ^ P6 ^ P7, k2 = (P5 & P6) | (P7 & (P5 | P6));
    uint32_t s3 = s1 ^ s2 ^ P8, k3 = (s1 & s2) | (P8 & (s1 | s2));
    uint32_t n0 = s3 ^ P9,      k4 = s3 & P9;
    uint32_t s4 = k1 ^ k2 ^ k3, k5 = (k1 & k2) | (k3 & (k1 | k2));
    uint32_t n1 = s4 ^ k4,      k6 = s4 & k4;
    Bn4 r; r.n0 = n0; r.n1 = n1; r.n2 = k5 ^ k6; r.n3 = k5 & k6; return r;
}

template <int SUB>
__device__ __forceinline__ uint32_t thin_rows(const uint32_t* __restrict__ rowA,
                                              const uint32_t* __restrict__ rowC,
                                              const uint32_t* __restrict__ rowB,
                                              uint32_t* __restrict__ dst, int w0) {
    uint32_t a[10], c[10], b[10];
    #pragma unroll
    for (int i = 0; i < 10; ++i) {
        int w = w0 - 1 + i;
        bool ok = (w >= 0) && (w < WW);
        a[i] = ok ? rowA[w] : 0u;
        c[i] = ok ? rowC[w] : 0u;
        b[i] = ok ? rowB[w] : 0u;
    }
    uint32_t ch = 0;
    #pragma unroll
    for (int i = 0; i < 8; ++i) {
        uint32_t aL = a[i], aM = a[i + 1], aR = a[i + 2];
        uint32_t cL = c[i], cM = c[i + 1], cR = c[i + 2];
        uint32_t bL = b[i], bM = b[i + 1], bR = b[i + 2];
        uint32_t P2 = aM, P6 = bM;
        uint32_t P3 = shE(aM, aR), P4 = shE(cM, cR), P5 = shE(bM, bR);
        uint32_t P7 = shW(bL, bM), P8 = shW(cL, cM), P9 = shW(aL, aM);
        Bn4 n = bn8(P2, P3, P4, P5, P6, P7, P8, P9);
        uint32_t ge2 = n.n1 | n.n2 | n.n3;
        uint32_t ge7 = n.n3 | (n.n0 & n.n1 & n.n2);
        uint32_t condB = ge2 & ~ge7;
        uint32_t t, acc, multi;
        acc = ~P2 & P3; multi = 0u;
        t = ~P3 & P4; multi |= acc & t; acc |= t;
        t = ~P4 & P5; multi |= acc & t; acc |= t;
        t = ~P5 & P6; multi |= acc & t; acc |= t;
        t = ~P6 & P7; multi |= acc & t; acc |= t;
        t = ~P7 & P8; multi |= acc & t; acc |= t;
        t = ~P8 & P9; multi |= acc & t; acc |= t;
        t = ~P9 & P2; multi |= acc & t; acc |= t;
        uint32_t A1 = acc & ~multi;
        uint32_t e1, e2;
        if (SUB == 0) { e1 = ~(P2 & P4 & P6); e2 = ~(P4 & P6 & P8); }
        else          { e1 = ~(P2 & P4 & P8); e2 = ~(P2 & P6 & P8); }
        uint32_t rem = cM & condB & A1 & e1 & e2;
        dst[w0 + i] = cM ^ rem;
        ch |= rem;
    }
    return ch;
}

__device__ __forceinline__ void endpoint_rows(const uint32_t* __restrict__ rowA,
                                              const uint32_t* __restrict__ rowC,
                                              const uint32_t* __restrict__ rowB,
                                              int img, int gy, int w0) {
    uint32_t a[10], c[10], b[10];
    #pragma unroll
    for (int i = 0; i < 10; ++i) {
        int w = w0 - 1 + i;
        bool ok = (w >= 0) && (w < WW);
        a[i] = ok ? rowA[w] : 0u;
        c[i] = ok ? rowC[w] : 0u;
        b[i] = ok ? rowB[w] : 0u;
    }
    #pragma unroll
    for (int i = 0; i < 8; ++i) {
        uint32_t aL = a[i], aM = a[i + 1], aR = a[i + 2];
        uint32_t cL = c[i], cM = c[i + 1], cR = c[i + 2];
        uint32_t bL = b[i], bM = b[i + 1], bR = b[i + 2];
        uint32_t P2 = aM, P6 = bM;
        uint32_t P3 = shE(aM, aR), P4 = shE(cM, cR), P5 = shE(bM, bR);
        uint32_t P7 = shW(bL, bM), P8 = shW(cL, cM), P9 = shW(aL, aM);
        Bn4 n = bn8(P2, P3, P4, P5, P6, P7, P8, P9);
        g_cbits[img][gy][w0 + i] = cM & n.n0 & ~(n.n1 | n.n2 | n.n3);
    }
}

// ---------------------------------------------------------------------------
// SMEM-resident cluster thinning (proven round-5 code, unchanged)
// ---------------------------------------------------------------------------
template <int ROWS>
struct ThinSmem {
    uint32_t img[2][ROWS][WP];   // ping-pong tiles, padded stride
    uint32_t zero[WP];
    uint8_t  rowch[3][ROWS];     // rolling per-row change flags
    int      sflag;
};

template <int NC, int ROWS, int NTHR, typename SM>
__device__ void thin_main(SM* sm, const float* __restrict__ pred) {
    cg::cluster_group cluster = cg::this_cluster();
    const int tid  = threadIdx.x;
    const int lane = tid & 31;
    const int warp = tid >> 5;
    const int rank = (int)cluster.block_rank();
    const int img  = blockIdx.x / NC;
    int* flag = &g_flag[img * MAXIT];

    // ---- pack phase: threshold pred into sm->img[0] (float4 + shfl-OR) ----
    constexpr int NWARP = NTHR / 32;
    for (int r = warp; r < ROWS; r += NWARP) {
        const float4* row = (const float4*)(pred + ((size_t)img * HH + (size_t)rank * ROWS + r) * WPX);
        #pragma unroll
        for (int step = 0; step < 8; ++step) {
            float4 v = row[step * 32 + lane];
            uint32_t nib = (v.x >= 0.5f ? 1u : 0u) | (v.y >= 0.5f ? 2u : 0u)
                         | (v.z >= 0.5f ? 4u : 0u) | (v.w >= 0.5f ? 8u : 0u);
            uint32_t x = nib << (4 * (lane & 7));
            x |= __shfl_xor_sync(0xffffffffu, x, 1);
            x |= __shfl_xor_sync(0xffffffffu, x, 2);
            x |= __shfl_xor_sync(0xffffffffu, x, 4);
            if ((lane & 7) == 0) sm->img[0][r][step * 4 + (lane >> 3)] = x;
        }
    }
    if (tid < WP) sm->zero[tid] = 0u;
    if (rank == 0) { for (int i = tid; i < MAXIT; i += NTHR) flag[i] = 0; }
    if (blockIdx.x == 0 && tid == 0) g_count = 0;
    __threadfence();
    cluster.sync();

    SM* pprev = (rank > 0)      ? (SM*)cluster.map_shared_rank(sm, rank - 1) : nullptr;
    SM* pnext = (rank < NC - 1) ? (SM*)cluster.map_shared_rank(sm, rank + 1) : nullptr;

    const int ly = tid >> 2;
    const int w0 = (tid & 3) * 8;

    int cur = 0;
    for (int iter = 0; iter < MAXIT; ++iter) {
        if (tid == 0) sm->sflag = 0;
        __syncthreads();

        // ---- substep 0: img[0] -> img[1] ----
        {
            bool recompute = true;
            if (iter > 0) {
                int p1 = (cur + 2) % 3, p2 = (cur + 1) % 3;
                unsigned d = (unsigned)sm->rowch[p1][ly] | (unsigned)sm->rowch[p2][ly];
                if (ly > 0)        d |= (unsigned)sm->rowch[p1][ly - 1] | (unsigned)sm->rowch[p2][ly - 1];
                else if (pprev)    d |= (unsigned)pprev->rowch[p1][ROWS - 1] | (unsigned)pprev->rowch[p2][ROWS - 1];
                if (ly < ROWS - 1) d |= (unsigned)sm->rowch[p1][ly + 1] | (unsigned)sm->rowch[p2][ly + 1];
                else if (pnext)    d |= (unsigned)pnext->rowch[p1][0] | (unsigned)pnext->rowch[p2][0];
                recompute = (d != 0u);
            }
            uint32_t ch = 0;
            if (recompute) {
                const uint32_t* rA = (ly > 0) ? sm->img[0][ly - 1]
                                  : (pprev ? pprev->img[0][ROWS - 1] : sm->zero);
                const uint32_t* rB = (ly < ROWS - 1) ? sm->img[0][ly + 1]
                                  : (pnext ? pnext->img[0][0] : sm->zero);
                ch = thin_rows<0>(rA, sm->img[0][ly], rB, sm->img[1][ly], w0);
            }
            unsigned bal = __ballot_sync(0xffffffffu, ch != 0u);
            if ((tid & 3) == 0)
                sm->rowch[cur][ly] = (uint8_t)(((bal >> (lane & 28)) & 0xFu) ? 1 : 0);
            if (bal && lane == 0) sm->sflag = 1;
        }
        cluster.sync();
        cur = (cur + 1) % 3;

        // ---- substep 1: img[1] -> img[0] ----
        {
            bool recompute = true;
            if (iter > 0) {
                int p1 = (cur + 2) % 3, p2 = (cur + 1) % 3;
                unsigned d = (unsigned)sm->rowch[p1][ly] | (unsigned)sm->rowch[p2][ly];
                if (ly > 0)        d |= (unsigned)sm->rowch[p1][ly - 1] | (unsigned)sm->rowch[p2][ly - 1];
                else if (pprev)    d |= (unsigned)pprev->rowch[p1][ROWS - 1] | (unsigned)pprev->rowch[p2][ROWS - 1];
                if (ly < ROWS - 1) d |= (unsigned)sm->rowch[p1][ly + 1] | (unsigned)sm->rowch[p2][ly + 1];
                else if (pnext)    d |= (unsigned)pnext->rowch[p1][0] | (unsigned)pnext->rowch[p2][0];
                recompute = (d != 0u);
            }
            uint32_t ch = 0;
            if (recompute) {
                const uint32_t* rA = (ly > 0) ? sm->img[1][ly - 1]
                                  : (pprev ? pprev->img[1][ROWS - 1] : sm->zero);
                const uint32_t* rB = (ly < ROWS - 1) ? sm->img[1][ly + 1]
                                  : (pnext ? pnext->img[1][0] : sm->zero);
                ch = thin_rows<1>(rA, sm->img[1][ly], rB, sm->img[0][ly], w0);
            }
            unsigned bal = __ballot_sync(0xffffffffu, ch != 0u);
            if ((tid & 3) == 0)
                sm->rowch[cur][ly] = (uint8_t)(((bal >> (lane & 28)) & 0xFu) ? 1 : 0);
            if (bal && lane == 0) sm->sflag = 1;
        }
        __syncthreads();
        if (tid == 0 && sm->sflag) { atomicOr(&flag[iter], 1); __threadfence(); }
        cluster.sync();
        cur = (cur + 1) % 3;
        if (__ldcg(&flag[iter]) == 0) break;
    }

    // ---- fused endpoint extraction from img[0] ----
    {
        const uint32_t* rA = (ly > 0) ? sm->img[0][ly - 1]
                          : (pprev ? pprev->img[0][ROWS - 1] : sm->zero);
        const uint32_t* rB = (ly < ROWS - 1) ? sm->img[0][ly + 1]
                          : (pnext ? pnext->img[0][0] : sm->zero);
        endpoint_rows(rA, sm->img[0][ly], rB, img, rank * ROWS + ly, w0);
    }
    cluster.sync();
}

__global__ void __cluster_dims__(16, 1, 1) __launch_bounds__(256, 1)
k_thin16(const float* __restrict__ pred) {
    __shared__ ThinSmem<64> sm;
    thin_main<16, 64, 256>(&sm, pred);
}

__global__ void __cluster_dims__(8, 1, 1) __launch_bounds__(512, 1)
k_thin8(const float* __restrict__ pred) {
    __shared__ ThinSmem<128> sm;
    thin_main<8, 128, 512>(&sm, pred);
}

// ---------------------------------------------------------------------------
// K2: weight + BCE with DECOUPLED layouts.
// Phase 1: per-thread word mapping builds 4 bit-planes + coverage -> smem.
// Phase 2: per-thread consecutive-pixel mapping -> fully coalesced loads.
// Last block performs the deterministic final reduction.
// ---------------------------------------------------------------------------
#define FA3(a, b, c, s, cy) { uint32_t _x = (a) ^ (b); (s) = _x ^ (c); (cy) = ((a) & (b)) | ((c) & _x); }

__global__ void __launch_bounds__(256) k_loss(const float* __restrict__ pred,
                                              const float* __restrict__ targ,
                                              float* __restrict__ out) {
    const int tid = threadIdx.x;
    const int img = blockIdx.x >> 7;
    const int y0  = (blockIdx.x & 127) * 8;      // block covers rows y0..y0+7
    const uint32_t* C = &g_cbits[img][0][0];

    __shared__ uint32_t tile[16][WW + 1];        // cbits rows y0-4 .. y0+11
    __shared__ uint32_t splanes[256 * 9];        // per word: 8 plane words + coverage
    #pragma unroll
    for (int k = 0; k < 2; ++k) {
        int idx = tid + k * 256;
        int sr = idx >> 5, sw = idx & 31;
        int gy = y0 - 4 + sr;
        tile[sr][sw] = (gy >= 0 && gy < HH) ? C[gy * WW + sw] : 0u;
    }
    __syncthreads();

    // ---- phase 1: this thread owns word (row lr, word w) of the block ----
    {
        const int w = tid & 31, lr = tid >> 5;
        uint32_t rlo[9], rhi[9], orAll = 0;
        #pragma unroll
        for (int d = 0; d < 9; ++d) {
            uint32_t M = tile[lr + d][w];
            uint32_t L = (w > 0)  ? tile[lr + d][w - 1] : 0u;
            uint32_t R = (w < 31) ? tile[lr + d][w + 1] : 0u;
            rlo[d] = (L >> 28) | (M << 4);
            rhi[d] = (M >> 28) | ((R & 0xFu) << 4);
            orAll |= rlo[d] | rhi[d];
        }
        uint32_t* P = &splanes[tid * 9];
        if (orAll) {
            uint32_t s1, c1, s2, c2, s3, c3, c4, s5, c5, c6;
            FA3(rlo[0], rlo[1], rlo[2], s1, c1);
            FA3(rlo[3], rlo[4], rlo[5], s2, c2);
            FA3(rlo[6], rlo[7], rlo[8], s3, c3);
            uint32_t S0l, S1l, S2l, S3l;
            FA3(s1, s2, s3, S0l, c4);
            FA3(c1, c2, c3, s5, c5);
            S1l = s5 ^ c4; c6 = s5 & c4;
            S2l = c5 ^ c6; S3l = c5 & c6;
            P[0] = S0l; P[1] = S1l; P[2] = S2l; P[3] = S3l;
            FA3(rhi[0], rhi[1], rhi[2], s1, c1);
            FA3(rhi[3], rhi[4], rhi[5], s2, c2);
            FA3(rhi[6], rhi[7], rhi[8], s3, c3);
            uint32_t S0h, S1h, S2h, S3h;
            FA3(s1, s2, s3, S0h, c4);
            FA3(c1, c2, c3, s5, c5);
            S1h = s5 ^ c4; c6 = s5 & c4;
            S2h = c5 ^ c6; S3h = c5 & c6;
            P[4] = S0h; P[5] = S1h; P[6] = S2h; P[7] = S3h;
        }
        P[8] = orAll;
    }
    __syncthreads();

    // ---- phase 2: consecutive-pixel mapping, coalesced streaming ----
    // Block pixels: [blockIdx.x*8192, +8192). Pass p: thread reads float4 at
    // local px = p*1024 + tid*4  ->  word = p*32 + (tid>>3), k = (tid&7)*4+j.
    const float4* p4 = (const float4*)pred + (size_t)blockIdx.x * 2048;
    const float4* t4 = (const float4*)targ + (size_t)blockIdx.x * 2048;
    const int kbase = (tid & 7) * 4;
    float fsum = 0.0f;

    float4 pv = __ldcs(p4 + tid), tv = __ldcs(t4 + tid);
    #pragma unroll
    for (int p = 0; p < 8; ++p) {
        float4 pn, tn;
        if (p < 7) { pn = __ldcs(p4 + (p + 1) * 256 + tid); tn = __ldcs(t4 + (p + 1) * 256 + tid); }
        const uint32_t* P = &splanes[(p * 32 + (tid >> 3)) * 9];
        uint32_t cov = P[8];
        float pa[4] = {pv.x, pv.y, pv.z, pv.w};
        float ta[4] = {tv.x, tv.y, tv.z, tv.w};
        #pragma unroll
        for (int j = 0; j < 4; ++j) {
            float pp = pa[j], tt = ta[j];
            float Lb = -(tt * __logf(pp) + (1.0f - tt) * __logf(1.0f - pp));
            float Wt = 1.0f;
            if (cov) {
                int k = kbase + j;
                int nsum = __popc(__funnelshift_r(P[0], P[4], k) & 0x1FFu)
                         + (__popc(__funnelshift_r(P[1], P[5], k) & 0x1FFu) << 1)
                         + (__popc(__funnelshift_r(P[2], P[6], k) & 0x1FFu) << 2)
                         + (__popc(__funnelshift_r(P[3], P[7], k) & 0x1FFu) << 3);
                if (nsum) Wt = 60.0f * (float)nsum;
            }
            fsum += Wt * Lb;
        }
        pv = pn; tv = tn;
    }

    __shared__ double sd[256];
    sd[tid] = (double)fsum;
    __syncthreads();
    #pragma unroll
    for (int s = 128; s > 0; s >>= 1) {
        if (tid < s) sd[tid] += sd[tid + s];
        __syncthreads();
    }
    __shared__ int slast;
    if (tid == 0) {
        g_partial[blockIdx.x] = sd[0];
        __threadfence();
        slast = (atomicAdd(&g_count, 1) == (int)gridDim.x - 1);
    }
    __syncthreads();
    if (!slast) return;

    // deterministic fixed-order final reduction of 1024 partials
    double v = __ldcg(&g_partial[tid]) + __ldcg(&g_partial[tid + 256])
             + __ldcg(&g_partial[tid + 512]) + __ldcg(&g_partial[tid + 768]);
    sd[tid] = v;
    __syncthreads();
    #pragma unroll
    for (int s = 128; s > 0; s >>= 1) {
        if (tid < s) sd[tid] += sd[tid + s];
        __syncthreads();
    }
    if (tid == 0) out[0] = (float)(sd[0] * (1.0 / ((double)IMGS * HH * WPX)));
}

// ---------------------------------------------------------------------------
extern "C" void kernel_launch(void* const* d_in, const int* in_sizes, int n_in,
                              void* d_out, int out_size) {
    (void)in_sizes; (void)n_in; (void)out_size;
    const float* pred = (const float*)d_in[0];
    const float* targ = (const float*)d_in[1];
    float* out = (float*)d_out;

    cudaError_t e = cudaFuncSetAttribute(
        (const void*)k_thin16, cudaFuncAttributeNonPortableClusterSizeAllowed, 1);
    if (e == cudaSuccess) {
        k_thin16<<<128, 256>>>(pred);
    } else {
        (void)cudaGetLastError();   // clear sticky error before capture continues
        k_thin8<<<64, 512>>>(pred);
    }

    k_loss<<<1024, 256>>>(pred, targ, out);
}